// round 5
// baseline (speedup 1.0000x reference)
#include <cuda_runtime.h>
#include <cstdint>

#define HW  4096
#define DIN 256
#define DK  64
#define DV  256
#define NB  4

// Scratch (device globals: no allocation allowed)
__device__ float g_Q[NB * DK * HW];     // raw Q     [b][k][hw]
__device__ float g_Khi[NB * DK * HW];   // tf32 hi K [b][k][hw]
__device__ float g_Klo[NB * DK * HW];   // tf32 lo K [b][k][hw]
__device__ float g_Vr[NB * DV * HW];    // tf32 rna V[b][v][hw]

// ---------------------------------------------------------------------------
// helpers
// ---------------------------------------------------------------------------
__device__ __forceinline__ uint32_t tf32u(float x) {
    uint32_t r; asm("cvt.rna.tf32.f32 %0, %1;" : "=r"(r) : "f"(x)); return r;
}
__device__ __forceinline__ float tf32f(float x) {
    return __uint_as_float(tf32u(x));
}
__device__ __forceinline__ uint32_t smem_u32(const void* p) {
    uint32_t r;
    asm("{ .reg .u64 t; cvta.to.shared.u64 t, %1; cvt.u32.u64 %0, t; }"
        : "=r"(r) : "l"(p));
    return r;
}
__device__ __forceinline__ void cpa16(uint32_t dst, const float* src) {
    asm volatile("cp.async.cg.shared.global [%0], [%1], 16;"
                 :: "r"(dst), "l"(__cvta_generic_to_global(src)) : "memory");
}
#define CP_COMMIT() asm volatile("cp.async.commit_group;" ::: "memory")
#define CP_WAIT0()  asm volatile("cp.async.wait_group 0;" ::: "memory")

__device__ __forceinline__ void mma16n8k8(float c[4], const uint32_t a[4],
                                          uint32_t b0, uint32_t b1) {
    asm volatile(
        "mma.sync.aligned.m16n8k8.row.col.f32.tf32.tf32.f32 "
        "{%0,%1,%2,%3}, {%4,%5,%6,%7}, {%8,%9}, {%0,%1,%2,%3};"
        : "+f"(c[0]), "+f"(c[1]), "+f"(c[2]), "+f"(c[3])
        : "r"(a[0]), "r"(a[1]), "r"(a[2]), "r"(a[3]), "r"(b0), "r"(b1));
}

// ---------------------------------------------------------------------------
// Projection GEMM: Out[b][r][p] = sum_c W[r][c] * X[b][c][p]
// sel 0: raw -> g_Q;  sel 1: tf32 split -> g_Khi/g_Klo;  sel 2: rna -> g_Vr
// ---------------------------------------------------------------------------
__global__ __launch_bounds__(256) void proj_kernel(
    const float* __restrict__ W, const float* __restrict__ X, int sel)
{
    __shared__ __align__(16) float Wt[16][68];
    __shared__ __align__(16) float Xt[16][64];

    float* Out = (sel == 0) ? g_Q : (sel == 1) ? g_Khi : g_Vr;
    const int R = (sel == 2) ? DV : DK;

    const int t  = threadIdx.x;
    const int b  = blockIdx.z;
    const int r0 = blockIdx.y * 64;
    const int p0 = blockIdx.x * 64;

    const float* Xb = X + (size_t)b * DIN * HW;
    float*       Ob = Out + (size_t)b * R * HW;

    const int tr = t >> 4;
    const int tc = t & 15;

    float acc[4][4];
#pragma unroll
    for (int i = 0; i < 4; i++)
#pragma unroll
        for (int j = 0; j < 4; j++) acc[i][j] = 0.f;

    for (int ck = 0; ck < DIN; ck += 16) {
        const int wc = t & 15;
        const int wr = t >> 4;
#pragma unroll
        for (int i = 0; i < 4; i++)
            Wt[wc][wr + 16 * i] = W[(r0 + wr + 16 * i) * DIN + ck + wc];
        const int xp = t & 63;
        const int xc = t >> 6;
#pragma unroll
        for (int i = 0; i < 4; i++)
            Xt[xc + 4 * i][xp] = Xb[(size_t)(ck + xc + 4 * i) * HW + p0 + xp];
        __syncthreads();

#pragma unroll
        for (int c = 0; c < 16; c++) {
            float4 w4 = *(const float4*)&Wt[c][tr * 4];
            float4 x4 = *(const float4*)&Xt[c][tc * 4];
            float wa[4] = {w4.x, w4.y, w4.z, w4.w};
            float xa[4] = {x4.x, x4.y, x4.z, x4.w};
#pragma unroll
            for (int i = 0; i < 4; i++)
#pragma unroll
                for (int j = 0; j < 4; j++) acc[i][j] += wa[i] * xa[j];
        }
        __syncthreads();
    }

    if (sel == 1) {
        float* Ob2 = g_Klo + (size_t)b * DK * HW;
#pragma unroll
        for (int i = 0; i < 4; i++) {
            float4 h, l;
            h.x = tf32f(acc[i][0]); l.x = tf32f(acc[i][0] - h.x);
            h.y = tf32f(acc[i][1]); l.y = tf32f(acc[i][1] - h.y);
            h.z = tf32f(acc[i][2]); l.z = tf32f(acc[i][2] - h.z);
            h.w = tf32f(acc[i][3]); l.w = tf32f(acc[i][3] - h.w);
            size_t off = (size_t)(r0 + tr * 4 + i) * HW + p0 + tc * 4;
            *(float4*)&Ob[off]  = h;
            *(float4*)&Ob2[off] = l;
        }
    } else if (sel == 2) {
#pragma unroll
        for (int i = 0; i < 4; i++) {
            float4 o = make_float4(tf32f(acc[i][0]), tf32f(acc[i][1]),
                                   tf32f(acc[i][2]), tf32f(acc[i][3]));
            *(float4*)&Ob[(size_t)(r0 + tr * 4 + i) * HW + p0 + tc * 4] = o;
        }
    } else {
#pragma unroll
        for (int i = 0; i < 4; i++) {
            float4 o = make_float4(acc[i][0], acc[i][1], acc[i][2], acc[i][3]);
            *(float4*)&Ob[(size_t)(r0 + tr * 4 + i) * HW + p0 + tc * 4] = o;
        }
    }
}

// ---------------------------------------------------------------------------
// tf32 mma.sync flash attention, 64-query CTAs, 2 CTAs/SM, cp.async fills.
// 256 threads = 8 warps; key tile = 32.
//   S phase:  warp (mg = w>>2, ng = w&3) -> S[32m x 8n]
//   AV phase: warp (mg = w>>2, vg = w&3) -> O[32m x 64v] (64 fp32 regs/thr)
// SMEM (floats): QHI/QLO [k][m] s68, KHI/KLO [k][n] s40, V [v][n] s36,
//                P [n][m] s68.   All fragment access patterns conflict-free.
// ---------------------------------------------------------------------------
#define QS_STR 68
#define KS_STR 40
#define VS_STR 36
#define PS_STR 68
#define OFF_QHI 0
#define OFF_QLO 4352
#define OFF_KHI 8704
#define OFF_KLO 11264
#define OFF_VS  13824
#define OFF_PT  23040
#define SMEM_FLOATS 25216   // 100864 bytes

__global__ __launch_bounds__(256, 2) void attn_mma_kernel(float* __restrict__ Out)
{
    extern __shared__ float sm[];
    __shared__ float s_part[64][4];
    __shared__ float s_inv[64];

    float* QHI = sm + OFF_QHI;
    float* QLO = sm + OFF_QLO;
    float* KHI = sm + OFF_KHI;
    float* KLO = sm + OFF_KLO;
    float* VS  = sm + OFF_VS;
    float* PT  = sm + OFF_PT;

    const uint32_t SB     = smem_u32(sm);
    const uint32_t kh_dst = SB + OFF_KHI * 4;
    const uint32_t kl_dst = SB + OFF_KLO * 4;
    const uint32_t vs_dst = SB + OFF_VS * 4;

    const int t    = threadIdx.x;
    const int w    = t >> 5;
    const int lane = t & 31;
    const int mg   = w >> 2;          // 0..1 : 32-row group
    const int ng   = w & 3;           // 0..3 : 8-col group (S) / 64-v group (AV)
    const int lr   = lane >> 2;       // 0..7
    const int lc   = lane & 3;        // 0..3
    const int b    = blockIdx.y;
    const int p0   = blockIdx.x * 64;

    const float* Qb   = g_Q   + (size_t)b * DK * HW;
    const float* Khib = g_Khi + (size_t)b * DK * HW;
    const float* Klob = g_Klo + (size_t)b * DK * HW;
    const float* Vrb  = g_Vr  + (size_t)b * DV * HW;

    // ---- load + split Q tile [64 k][64 m] (once) ----
#pragma unroll
    for (int i = 0; i < 16; i++) {
        int idx = t + i * 256;
        int mm = idx & 63, kk = idx >> 6;
        float v  = Qb[(size_t)kk * HW + p0 + mm];
        float hi = tf32f(v);
        float lo = tf32f(v - hi);
        QHI[kk * QS_STR + mm] = hi;
        QLO[kk * QS_STR + mm] = lo;
    }

    float o[2][8][4];
#pragma unroll
    for (int mt = 0; mt < 2; mt++)
#pragma unroll
        for (int vt = 0; vt < 8; vt++)
#pragma unroll
            for (int j = 0; j < 4; j++) o[mt][vt][j] = 0.f;
    float rs[4] = {0.f, 0.f, 0.f, 0.f};

    for (int kt = 0; kt < 128; kt++) {
        const int n0 = kt * 32;
        __syncthreads();   // prev AV done: V/P/K buffers free (also orders Q stores)

        // ---- cp.async fills: K hi/lo [64k][32n], V [256v][32n] ----
#pragma unroll
        for (int j = 0; j < 2; j++) {
            int chunk = t + j * 256;
            int row = chunk >> 3, c4 = chunk & 7;
            uint32_t doff = (uint32_t)(row * KS_STR + c4 * 4) * 4;
            const float* s = Khib + (size_t)row * HW + n0 + c4 * 4;
            cpa16(kh_dst + doff, s);
            cpa16(kl_dst + doff, Klob + (size_t)row * HW + n0 + c4 * 4);
        }
#pragma unroll
        for (int j = 0; j < 8; j++) {
            int chunk = t + j * 256;
            int row = chunk >> 3, c4 = chunk & 7;
            cpa16(vs_dst + (uint32_t)(row * VS_STR + c4 * 4) * 4,
                  Vrb + (size_t)row * HW + n0 + c4 * 4);
        }
        CP_COMMIT();
        CP_WAIT0();
        __syncthreads();   // tiles visible CTA-wide

        // ---- S = Qhi*Khi + Qhi*Klo + Qlo*Khi : warp -> S[32m x 8n] ----
        float c[2][4];
#pragma unroll
        for (int mt = 0; mt < 2; mt++)
#pragma unroll
            for (int j = 0; j < 4; j++) c[mt][j] = 0.f;

#pragma unroll
        for (int k8 = 0; k8 < 8; k8++) {
            const int ka = k8 * 8 + lc;
            const int bc = ng * 8 + lr;
            uint32_t bh0 = __float_as_uint(KHI[ka * KS_STR + bc]);
            uint32_t bh1 = __float_as_uint(KHI[(ka + 4) * KS_STR + bc]);
            uint32_t bl0 = __float_as_uint(KLO[ka * KS_STR + bc]);
            uint32_t bl1 = __float_as_uint(KLO[(ka + 4) * KS_STR + bc]);
#pragma unroll
            for (int mt = 0; mt < 2; mt++) {
                const int ar = mg * 32 + mt * 16 + lr;
                uint32_t ahi[4], alo[4];
                ahi[0] = __float_as_uint(QHI[ka * QS_STR + ar]);
                ahi[1] = __float_as_uint(QHI[ka * QS_STR + ar + 8]);
                ahi[2] = __float_as_uint(QHI[(ka + 4) * QS_STR + ar]);
                ahi[3] = __float_as_uint(QHI[(ka + 4) * QS_STR + ar + 8]);
                alo[0] = __float_as_uint(QLO[ka * QS_STR + ar]);
                alo[1] = __float_as_uint(QLO[ka * QS_STR + ar + 8]);
                alo[2] = __float_as_uint(QLO[(ka + 4) * QS_STR + ar]);
                alo[3] = __float_as_uint(QLO[(ka + 4) * QS_STR + ar + 8]);
                mma16n8k8(c[mt], ahi, bh0, bh1);
                mma16n8k8(c[mt], ahi, bl0, bl1);
                mma16n8k8(c[mt], alo, bh0, bh1);
            }
        }

        // ---- exp (max-free), P -> SMEM [n][m] (tf32), rowsums ----
#pragma unroll
        for (int mt = 0; mt < 2; mt++) {
            const int row = mg * 32 + mt * 16 + lr;
            const int nb  = ng * 8 + 2 * lc;
            float e0 = tf32f(__expf(c[mt][0]));
            float e1 = tf32f(__expf(c[mt][1]));
            float e2 = tf32f(__expf(c[mt][2]));
            float e3 = tf32f(__expf(c[mt][3]));
            PT[nb * PS_STR + row]           = e0;
            PT[(nb + 1) * PS_STR + row]     = e1;
            PT[nb * PS_STR + row + 8]       = e2;
            PT[(nb + 1) * PS_STR + row + 8] = e3;
            rs[mt * 2 + 0] += e0 + e1;
            rs[mt * 2 + 1] += e2 + e3;
        }
        __syncthreads();   // P visible (K also free now)

        // ---- O += P * V^T : warp -> O[32m x 64v] ----
#pragma unroll
        for (int k8 = 0; k8 < 4; k8++) {
            const int ka = k8 * 8 + lc;
            uint32_t a[2][4];
#pragma unroll
            for (int mt = 0; mt < 2; mt++) {
                const int row = mg * 32 + mt * 16 + lr;
                a[mt][0] = __float_as_uint(PT[ka * PS_STR + row]);
                a[mt][1] = __float_as_uint(PT[ka * PS_STR + row + 8]);
                a[mt][2] = __float_as_uint(PT[(ka + 4) * PS_STR + row]);
                a[mt][3] = __float_as_uint(PT[(ka + 4) * PS_STR + row + 8]);
            }
#pragma unroll
            for (int vt = 0; vt < 8; vt++) {
                const int vcol = ng * 64 + vt * 8 + lr;
                uint32_t b0 = __float_as_uint(VS[vcol * VS_STR + ka]);
                uint32_t b1 = __float_as_uint(VS[vcol * VS_STR + ka + 4]);
                mma16n8k8(o[0][vt], a[0], b0, b1);
                mma16n8k8(o[1][vt], a[1], b0, b1);
            }
        }
    }

    // ---- rowsum reduction across lanes and ng groups ----
#pragma unroll
    for (int i = 0; i < 4; i++) {
        rs[i] += __shfl_xor_sync(0xffffffffu, rs[i], 1);
        rs[i] += __shfl_xor_sync(0xffffffffu, rs[i], 2);
    }
    if (lc == 0) {
#pragma unroll
        for (int i = 0; i < 4; i++) {
            int row = mg * 32 + (i >> 1) * 16 + (i & 1) * 8 + lr;
            s_part[row][ng] = rs[i];
        }
    }
    __syncthreads();
    if (t < 64)
        s_inv[t] = 1.0f / (s_part[t][0] + s_part[t][1] + s_part[t][2] + s_part[t][3]);
    __syncthreads();

    // ---- normalize + store ----
    float* Ob = Out + (size_t)b * DV * HW;
#pragma unroll
    for (int mt = 0; mt < 2; mt++) {
        const int r = mg * 32 + mt * 16 + lr;
        const float inv0 = s_inv[r];
        const float inv1 = s_inv[r + 8];
#pragma unroll
        for (int vt = 0; vt < 8; vt++) {
            const int v = ng * 64 + vt * 8 + 2 * lc;
            Ob[(size_t)v * HW + p0 + r]           = o[mt][vt][0] * inv0;
            Ob[(size_t)(v + 1) * HW + p0 + r]     = o[mt][vt][1] * inv0;
            Ob[(size_t)v * HW + p0 + r + 8]       = o[mt][vt][2] * inv1;
            Ob[(size_t)(v + 1) * HW + p0 + r + 8] = o[mt][vt][3] * inv1;
        }
    }
}

// ---------------------------------------------------------------------------
extern "C" void kernel_launch(void* const* d_in, const int* in_sizes, int n_in,
                              void* d_out, int out_size)
{
    const float* x  = (const float*)d_in[0];
    const float* qw = (const float*)d_in[1];
    const float* kw = (const float*)d_in[2];
    const float* vw = (const float*)d_in[3];
    float* out = (float*)d_out;

    proj_kernel<<<dim3(64, 1, NB), 256>>>(qw, x, 0);
    proj_kernel<<<dim3(64, 1, NB), 256>>>(kw, x, 1);
    proj_kernel<<<dim3(64, 4, NB), 256>>>(vw, x, 2);

    const size_t smem_bytes = (size_t)SMEM_FLOATS * sizeof(float);
    cudaFuncSetAttribute(attn_mma_kernel,
                         cudaFuncAttributeMaxDynamicSharedMemorySize,
                         (int)smem_bytes);
    attn_mma_kernel<<<dim3(64, NB), 256, smem_bytes>>>(out);
}

// round 6
// speedup vs baseline: 1.4860x; 1.4860x over previous
#include <cuda_runtime.h>
#include <cstdint>

#define HW  4096
#define DIN 256
#define DK  64
#define DV  256
#define NB  4

// Scratch (device globals: no allocation allowed)
__device__ float g_Q[NB * DK * HW];     // raw Q      [b][k][hw]
__device__ float g_Khi[NB * DK * HW];   // tf32 hi K  [b][k][hw]
__device__ float g_Klo[NB * DK * HW];   // tf32 lo K  [b][k][hw]
__device__ float g_Vr[NB * DV * HW];    // tf32 rna V [b][v][hw]

// ---------------------------------------------------------------------------
// helpers
// ---------------------------------------------------------------------------
__device__ __forceinline__ uint32_t tf32u(float x) {
    uint32_t r; asm("cvt.rna.tf32.f32 %0, %1;" : "=r"(r) : "f"(x)); return r;
}
__device__ __forceinline__ float tf32f(float x) {
    return __uint_as_float(tf32u(x));
}
__device__ __forceinline__ uint32_t smem_u32(const void* p) {
    uint32_t r;
    asm("{ .reg .u64 t; cvta.to.shared.u64 t, %1; cvt.u32.u64 %0, t; }"
        : "=r"(r) : "l"(p));
    return r;
}
__device__ __forceinline__ void cpa16(uint32_t dst, const float* src) {
    asm volatile("cp.async.cg.shared.global [%0], [%1], 16;"
                 :: "r"(dst), "l"(__cvta_generic_to_global(src)) : "memory");
}
#define CP_COMMIT() asm volatile("cp.async.commit_group;" ::: "memory")
#define CP_WAIT(n)  asm volatile("cp.async.wait_group %0;" :: "n"(n) : "memory")

__device__ __forceinline__ void mma16n8k8(float c[4], const uint32_t a[4],
                                          uint32_t b0, uint32_t b1) {
    asm volatile(
        "mma.sync.aligned.m16n8k8.row.col.f32.tf32.tf32.f32 "
        "{%0,%1,%2,%3}, {%4,%5,%6,%7}, {%8,%9}, {%0,%1,%2,%3};"
        : "+f"(c[0]), "+f"(c[1]), "+f"(c[2]), "+f"(c[3])
        : "r"(a[0]), "r"(a[1]), "r"(a[2]), "r"(a[3]), "r"(b0), "r"(b1));
}

// ---------------------------------------------------------------------------
// Projection GEMM: Out[b][r][p] = sum_c W[r][c] * X[b][c][p]
// sel 0: raw -> g_Q;  sel 1: tf32 split -> g_Khi/g_Klo;  sel 2: rna -> g_Vr
// ---------------------------------------------------------------------------
__global__ __launch_bounds__(256) void proj_kernel(
    const float* __restrict__ W, const float* __restrict__ X, int sel)
{
    __shared__ __align__(16) float Wt[16][68];
    __shared__ __align__(16) float Xt[16][64];

    float* Out = (sel == 0) ? g_Q : (sel == 1) ? g_Khi : g_Vr;
    const int R = (sel == 2) ? DV : DK;

    const int t  = threadIdx.x;
    const int b  = blockIdx.z;
    const int r0 = blockIdx.y * 64;
    const int p0 = blockIdx.x * 64;

    const float* Xb = X + (size_t)b * DIN * HW;
    float*       Ob = Out + (size_t)b * R * HW;

    const int tr = t >> 4;
    const int tc = t & 15;

    float acc[4][4];
#pragma unroll
    for (int i = 0; i < 4; i++)
#pragma unroll
        for (int j = 0; j < 4; j++) acc[i][j] = 0.f;

    for (int ck = 0; ck < DIN; ck += 16) {
        const int wc = t & 15;
        const int wr = t >> 4;
#pragma unroll
        for (int i = 0; i < 4; i++)
            Wt[wc][wr + 16 * i] = W[(r0 + wr + 16 * i) * DIN + ck + wc];
        const int xp = t & 63;
        const int xc = t >> 6;
#pragma unroll
        for (int i = 0; i < 4; i++)
            Xt[xc + 4 * i][xp] = Xb[(size_t)(ck + xc + 4 * i) * HW + p0 + xp];
        __syncthreads();

#pragma unroll
        for (int c = 0; c < 16; c++) {
            float4 w4 = *(const float4*)&Wt[c][tr * 4];
            float4 x4 = *(const float4*)&Xt[c][tc * 4];
            float wa[4] = {w4.x, w4.y, w4.z, w4.w};
            float xa[4] = {x4.x, x4.y, x4.z, x4.w};
#pragma unroll
            for (int i = 0; i < 4; i++)
#pragma unroll
                for (int j = 0; j < 4; j++) acc[i][j] += wa[i] * xa[j];
        }
        __syncthreads();
    }

    if (sel == 1) {
        float* Ob2 = g_Klo + (size_t)b * DK * HW;
#pragma unroll
        for (int i = 0; i < 4; i++) {
            float4 h, l;
            h.x = tf32f(acc[i][0]); l.x = tf32f(acc[i][0] - h.x);
            h.y = tf32f(acc[i][1]); l.y = tf32f(acc[i][1] - h.y);
            h.z = tf32f(acc[i][2]); l.z = tf32f(acc[i][2] - h.z);
            h.w = tf32f(acc[i][3]); l.w = tf32f(acc[i][3] - h.w);
            size_t off = (size_t)(r0 + tr * 4 + i) * HW + p0 + tc * 4;
            *(float4*)&Ob[off]  = h;
            *(float4*)&Ob2[off] = l;
        }
    } else if (sel == 2) {
#pragma unroll
        for (int i = 0; i < 4; i++) {
            float4 o = make_float4(tf32f(acc[i][0]), tf32f(acc[i][1]),
                                   tf32f(acc[i][2]), tf32f(acc[i][3]));
            *(float4*)&Ob[(size_t)(r0 + tr * 4 + i) * HW + p0 + tc * 4] = o;
        }
    } else {
#pragma unroll
        for (int i = 0; i < 4; i++) {
            float4 o = make_float4(acc[i][0], acc[i][1], acc[i][2], acc[i][3]);
            *(float4*)&Ob[(size_t)(r0 + tr * 4 + i) * HW + p0 + tc * 4] = o;
        }
    }
}

// ---------------------------------------------------------------------------
// tf32 mma.sync flash attention (R4 shape) + cp.async pipelined K/V loads.
// CTA = (batch, 128-query tile), 512 threads = 16 warps, 64-key tiles.
//   S phase:  warp (mg = w>>2, ng = w&3) -> S[32m x 16n]
//   AV phase: warp (mg = w>>2, vg = w&3) -> O[32m x 64v] (64 fp32 regs/thr)
// SMEM: Qhi/Qlo [m][k] s68, Khi/Klo [k][n] s72, V [v][n] s68, P [m][n] s68
// Pipeline (per tile): wait K -> S -> bar -> issue K[kt+1] -> exp/P ->
//                      wait V -> AV -> bar -> issue V[kt+1]
// ---------------------------------------------------------------------------
#define QS_STR 68
#define KS_STR 72
#define VS_STR 68
#define PS_STR 68
#define OFF_QHI 0
#define OFF_QLO (OFF_QHI + 128 * QS_STR)        //  8704
#define OFF_KHI (OFF_QLO + 128 * QS_STR)        // 17408
#define OFF_KLO (OFF_KHI + 64 * KS_STR)         // 22016
#define OFF_VS  (OFF_KLO + 64 * KS_STR)         // 26624
#define OFF_PS  (OFF_VS + 256 * VS_STR)         // 44032
#define SMEM_FLOATS (OFF_PS + 128 * PS_STR)     // 52736 -> 210944 B

__global__ __launch_bounds__(512, 1) void attn_mma_kernel(float* __restrict__ Out)
{
    extern __shared__ float sm[];
    __shared__ float s_part[128][4];
    __shared__ float s_inv[128];

    float* QHI = sm + OFF_QHI;
    float* QLO = sm + OFF_QLO;
    float* KHI = sm + OFF_KHI;
    float* KLO = sm + OFF_KLO;
    float* VS  = sm + OFF_VS;
    float* PS  = sm + OFF_PS;

    const uint32_t SB     = smem_u32(sm);
    const uint32_t kh_dst = SB + OFF_KHI * 4;
    const uint32_t kl_dst = SB + OFF_KLO * 4;
    const uint32_t vs_dst = SB + OFF_VS * 4;

    const int t    = threadIdx.x;
    const int w    = t >> 5;
    const int lane = t & 31;
    const int mg   = w >> 2;          // 0..3 : 32-row group
    const int ng   = w & 3;           // 0..3 : 16-col group (S) / 64-v group (AV)
    const int m0   = mg * 32;
    const int lr   = lane >> 2;       // 0..7
    const int lc   = lane & 3;        // 0..3
    const int b    = blockIdx.y;
    const int p0   = blockIdx.x * 128;

    const float* Qb   = g_Q   + (size_t)b * DK * HW;
    const float* Khib = g_Khi + (size_t)b * DK * HW;
    const float* Klob = g_Klo + (size_t)b * DK * HW;
    const float* Vrb  = g_Vr  + (size_t)b * DV * HW;

    // per-thread cp.async chunk coordinates
    const int krow0 = t >> 4;              // K: 64 rows x 16 chunks, 2 per thread
    const int kc4   = t & 15;
    const int vrow0 = t >> 4;              // V: 256 rows x 16 chunks, 8 per thread
    const int vc4   = t & 15;

    // ---- issue K[0] then V[0] ----
    {
        const int n0 = 0;
#pragma unroll
        for (int j = 0; j < 2; j++) {
            int row = krow0 + j * 32;
            uint32_t doff = (uint32_t)(row * KS_STR + kc4 * 4) * 4;
            cpa16(kh_dst + doff, Khib + (size_t)row * HW + n0 + kc4 * 4);
            cpa16(kl_dst + doff, Klob + (size_t)row * HW + n0 + kc4 * 4);
        }
        CP_COMMIT();
#pragma unroll
        for (int j = 0; j < 8; j++) {
            int row = vrow0 + j * 32;
            cpa16(vs_dst + (uint32_t)(row * VS_STR + vc4 * 4) * 4,
                  Vrb + (size_t)row * HW + n0 + vc4 * 4);
        }
        CP_COMMIT();
    }

    // ---- load + split Q tile [128 m][64 k] (overlaps K/V inflight) ----
#pragma unroll
    for (int i = 0; i < 16; i++) {
        int idx = t + i * 512;
        int mm = idx & 127, kk = idx >> 7;
        float v  = Qb[(size_t)kk * HW + p0 + mm];
        float hi = tf32f(v);
        float lo = tf32f(v - hi);
        QHI[mm * QS_STR + kk] = hi;
        QLO[mm * QS_STR + kk] = lo;
    }

    float o[2][8][4];
#pragma unroll
    for (int mt = 0; mt < 2; mt++)
#pragma unroll
        for (int vt = 0; vt < 8; vt++)
#pragma unroll
            for (int j = 0; j < 4; j++) o[mt][vt][j] = 0.f;
    float rs[4] = {0.f, 0.f, 0.f, 0.f};

    for (int kt = 0; kt < 64; kt++) {
        // ---- wait K[kt] (leave newest group in flight), make visible ----
        CP_WAIT(1);
        __syncthreads();

        // ---- S = Qhi*Khi + Qhi*Klo + Qlo*Khi : warp -> S[32m x 16n] ----
        float c[2][2][4];
#pragma unroll
        for (int mt = 0; mt < 2; mt++)
#pragma unroll
            for (int nt = 0; nt < 2; nt++)
#pragma unroll
                for (int j = 0; j < 4; j++) c[mt][nt][j] = 0.f;

#pragma unroll
        for (int k8 = 0; k8 < 8; k8++) {
            const int ka = k8 * 8 + lc;
            uint32_t ahi[2][4], alo[2][4];
#pragma unroll
            for (int mt = 0; mt < 2; mt++) {
                int ar = m0 + mt * 16 + lr;
                ahi[mt][0] = __float_as_uint(QHI[ar * QS_STR + ka]);
                ahi[mt][1] = __float_as_uint(QHI[(ar + 8) * QS_STR + ka]);
                ahi[mt][2] = __float_as_uint(QHI[ar * QS_STR + ka + 4]);
                ahi[mt][3] = __float_as_uint(QHI[(ar + 8) * QS_STR + ka + 4]);
                alo[mt][0] = __float_as_uint(QLO[ar * QS_STR + ka]);
                alo[mt][1] = __float_as_uint(QLO[(ar + 8) * QS_STR + ka]);
                alo[mt][2] = __float_as_uint(QLO[ar * QS_STR + ka + 4]);
                alo[mt][3] = __float_as_uint(QLO[(ar + 8) * QS_STR + ka + 4]);
            }
#pragma unroll
            for (int nt = 0; nt < 2; nt++) {
                int bc = ng * 16 + nt * 8 + lr;
                int br = k8 * 8 + lc;
                uint32_t bh0 = __float_as_uint(KHI[br * KS_STR + bc]);
                uint32_t bh1 = __float_as_uint(KHI[(br + 4) * KS_STR + bc]);
                uint32_t bl0 = __float_as_uint(KLO[br * KS_STR + bc]);
                uint32_t bl1 = __float_as_uint(KLO[(br + 4) * KS_STR + bc]);
#pragma unroll
                for (int mt = 0; mt < 2; mt++) {
                    mma16n8k8(c[mt][nt], ahi[mt], bh0, bh1);
                    mma16n8k8(c[mt][nt], ahi[mt], bl0, bl1);
                    mma16n8k8(c[mt][nt], alo[mt], bh0, bh1);
                }
            }
        }

        // ---- all warps done with K[kt]; start K[kt+1] load ----
        __syncthreads();
        if (kt < 63) {
            const int n0 = (kt + 1) * 64;
#pragma unroll
            for (int j = 0; j < 2; j++) {
                int row = krow0 + j * 32;
                uint32_t doff = (uint32_t)(row * KS_STR + kc4 * 4) * 4;
                cpa16(kh_dst + doff, Khib + (size_t)row * HW + n0 + kc4 * 4);
                cpa16(kl_dst + doff, Klob + (size_t)row * HW + n0 + kc4 * 4);
            }
            CP_COMMIT();
        }

        // ---- exp (max-free), P -> SMEM (tf32), rowsums ----
#pragma unroll
        for (int mt = 0; mt < 2; mt++) {
            int pr = m0 + mt * 16 + lr;
#pragma unroll
            for (int nt = 0; nt < 2; nt++) {
                int pc = ng * 16 + nt * 8 + 2 * lc;
                float e0 = tf32f(__expf(c[mt][nt][0]));
                float e1 = tf32f(__expf(c[mt][nt][1]));
                float e2 = tf32f(__expf(c[mt][nt][2]));
                float e3 = tf32f(__expf(c[mt][nt][3]));
                *(float2*)&PS[pr * PS_STR + pc]       = make_float2(e0, e1);
                *(float2*)&PS[(pr + 8) * PS_STR + pc] = make_float2(e2, e3);
                rs[mt * 2 + 0] += e0 + e1;
                rs[mt * 2 + 1] += e2 + e3;
            }
        }

        // ---- wait V[kt] (K[kt+1] may stay in flight), make V+P visible ----
        if (kt < 63) { CP_WAIT(1); } else { CP_WAIT(0); }
        __syncthreads();

        // ---- O += P * V^T : warp -> O[32m x 64v] ----
#pragma unroll
        for (int k8 = 0; k8 < 8; k8++) {
            const int ka = k8 * 8 + lc;
            uint32_t a[2][4];
#pragma unroll
            for (int mt = 0; mt < 2; mt++) {
                int ar = m0 + mt * 16 + lr;
                a[mt][0] = __float_as_uint(PS[ar * PS_STR + ka]);
                a[mt][1] = __float_as_uint(PS[(ar + 8) * PS_STR + ka]);
                a[mt][2] = __float_as_uint(PS[ar * PS_STR + ka + 4]);
                a[mt][3] = __float_as_uint(PS[(ar + 8) * PS_STR + ka + 4]);
            }
#pragma unroll
            for (int vt = 0; vt < 8; vt++) {
                int vcol = ng * 64 + vt * 8 + lr;
                int nrow = k8 * 8 + lc;
                uint32_t b0 = __float_as_uint(VS[vcol * VS_STR + nrow]);
                uint32_t b1 = __float_as_uint(VS[vcol * VS_STR + nrow + 4]);
                mma16n8k8(o[0][vt], a[0], b0, b1);
                mma16n8k8(o[1][vt], a[1], b0, b1);
            }
        }

        // ---- all warps done with V[kt] (and P); start V[kt+1] load ----
        __syncthreads();
        if (kt < 63) {
            const int n0 = (kt + 1) * 64;
#pragma unroll
            for (int j = 0; j < 8; j++) {
                int row = vrow0 + j * 32;
                cpa16(vs_dst + (uint32_t)(row * VS_STR + vc4 * 4) * 4,
                      Vrb + (size_t)row * HW + n0 + vc4 * 4);
            }
            CP_COMMIT();
        }
    }

    // ---- rowsum reduction across lanes and ng groups ----
#pragma unroll
    for (int i = 0; i < 4; i++) {
        rs[i] += __shfl_xor_sync(0xffffffffu, rs[i], 1);
        rs[i] += __shfl_xor_sync(0xffffffffu, rs[i], 2);
    }
    if (lc == 0) {
#pragma unroll
        for (int i = 0; i < 4; i++) {
            int row = m0 + (i >> 1) * 16 + (i & 1) * 8 + lr;
            s_part[row][ng] = rs[i];
        }
    }
    __syncthreads();
    if (t < 128)
        s_inv[t] = 1.0f / (s_part[t][0] + s_part[t][1] + s_part[t][2] + s_part[t][3]);
    __syncthreads();

    // ---- normalize + store ----
    float* Ob = Out + (size_t)b * DV * HW;
#pragma unroll
    for (int mt = 0; mt < 2; mt++) {
        int r = m0 + mt * 16 + lr;
        float inv0 = s_inv[r];
        float inv1 = s_inv[r + 8];
#pragma unroll
        for (int vt = 0; vt < 8; vt++) {
            int v = ng * 64 + vt * 8 + 2 * lc;
            Ob[(size_t)v * HW + p0 + r]            = o[mt][vt][0] * inv0;
            Ob[(size_t)(v + 1) * HW + p0 + r]      = o[mt][vt][1] * inv0;
            Ob[(size_t)v * HW + p0 + r + 8]        = o[mt][vt][2] * inv1;
            Ob[(size_t)(v + 1) * HW + p0 + r + 8]  = o[mt][vt][3] * inv1;
        }
    }
}

// ---------------------------------------------------------------------------
extern "C" void kernel_launch(void* const* d_in, const int* in_sizes, int n_in,
                              void* d_out, int out_size)
{
    const float* x  = (const float*)d_in[0];
    const float* qw = (const float*)d_in[1];
    const float* kw = (const float*)d_in[2];
    const float* vw = (const float*)d_in[3];
    float* out = (float*)d_out;

    proj_kernel<<<dim3(64, 1, NB), 256>>>(qw, x, 0);
    proj_kernel<<<dim3(64, 1, NB), 256>>>(kw, x, 1);
    proj_kernel<<<dim3(64, 4, NB), 256>>>(vw, x, 2);

    const size_t smem_bytes = (size_t)SMEM_FLOATS * sizeof(float);
    cudaFuncSetAttribute(attn_mma_kernel,
                         cudaFuncAttributeMaxDynamicSharedMemorySize,
                         (int)smem_bytes);
    attn_mma_kernel<<<dim3(32, NB), 512, smem_bytes>>>(out);
}

// round 7
// speedup vs baseline: 2.0559x; 1.3835x over previous
#include <cuda_runtime.h>
#include <cuda_fp16.h>
#include <cstdint>

#define HW  4096
#define DIN 256
#define DK  64
#define DV  256
#define NB  4

// Scratch (device globals: no allocation allowed)
__device__ float    g_Q[NB * DK * HW];            // raw Q [b][k][hw] fp32
__device__ uint32_t g_K2H[NB * (DK/2) * HW];      // K hi, fp16x2 packed along dk
__device__ uint32_t g_K2L[NB * (DK/2) * HW];      // K lo residual
__device__ uint32_t g_V2[NB * DV * (HW/2)];       // V fp16x2 packed along hw

// ---------------------------------------------------------------------------
// helpers
// ---------------------------------------------------------------------------
__device__ __forceinline__ uint32_t h2u(__half2 h) {
    return *reinterpret_cast<uint32_t*>(&h);
}
__device__ __forceinline__ uint32_t packh2(float lo_elem, float hi_elem) {
    __half2 h = __floats2half2_rn(lo_elem, hi_elem);  // .x = low half
    return h2u(h);
}
__device__ __forceinline__ uint32_t smem_u32(const void* p) {
    uint32_t r;
    asm("{ .reg .u64 t; cvta.to.shared.u64 t, %1; cvt.u32.u64 %0, t; }"
        : "=r"(r) : "l"(p));
    return r;
}
__device__ __forceinline__ void cpa16(uint32_t dst, const uint32_t* src) {
    asm volatile("cp.async.cg.shared.global [%0], [%1], 16;"
                 :: "r"(dst), "l"(__cvta_generic_to_global(src)) : "memory");
}
#define CP_COMMIT() asm volatile("cp.async.commit_group;" ::: "memory")
#define CP_WAIT(n)  asm volatile("cp.async.wait_group %0;" :: "n"(n) : "memory")

__device__ __forceinline__ void mma_f16(float c[4], const uint32_t a[4],
                                        uint32_t b0, uint32_t b1) {
    asm volatile(
        "mma.sync.aligned.m16n8k16.row.col.f32.f16.f16.f32 "
        "{%0,%1,%2,%3}, {%4,%5,%6,%7}, {%8,%9}, {%0,%1,%2,%3};"
        : "+f"(c[0]), "+f"(c[1]), "+f"(c[2]), "+f"(c[3])
        : "r"(a[0]), "r"(a[1]), "r"(a[2]), "r"(a[3]), "r"(b0), "r"(b1));
}

// ---------------------------------------------------------------------------
// Projection GEMM: Out[b][r][p] = sum_c W[r][c] * X[b][c][p]
// sel 0: raw fp32 -> g_Q
// sel 1: fp16 hi/lo split, packed along dk -> g_K2H / g_K2L
// sel 2: fp16, packed along hw -> g_V2
// ---------------------------------------------------------------------------
__global__ __launch_bounds__(256) void proj_kernel(
    const float* __restrict__ W, const float* __restrict__ X, int sel)
{
    __shared__ __align__(16) float Wt[16][68];
    __shared__ __align__(16) float Xt[16][64];

    const int R = (sel == 2) ? DV : DK;

    const int t  = threadIdx.x;
    const int b  = blockIdx.z;
    const int r0 = blockIdx.y * 64;
    const int p0 = blockIdx.x * 64;

    const float* Xb = X + (size_t)b * DIN * HW;

    const int tr = t >> 4;
    const int tc = t & 15;

    float acc[4][4];
#pragma unroll
    for (int i = 0; i < 4; i++)
#pragma unroll
        for (int j = 0; j < 4; j++) acc[i][j] = 0.f;

    for (int ck = 0; ck < DIN; ck += 16) {
        const int wc = t & 15;
        const int wr = t >> 4;
#pragma unroll
        for (int i = 0; i < 4; i++)
            Wt[wc][wr + 16 * i] = W[(r0 + wr + 16 * i) * DIN + ck + wc];
        const int xp = t & 63;
        const int xc = t >> 6;
#pragma unroll
        for (int i = 0; i < 4; i++)
            Xt[xc + 4 * i][xp] = Xb[(size_t)(ck + xc + 4 * i) * HW + p0 + xp];
        __syncthreads();

#pragma unroll
        for (int c = 0; c < 16; c++) {
            float4 w4 = *(const float4*)&Wt[c][tr * 4];
            float4 x4 = *(const float4*)&Xt[c][tc * 4];
            float wa[4] = {w4.x, w4.y, w4.z, w4.w};
            float xa[4] = {x4.x, x4.y, x4.z, x4.w};
#pragma unroll
            for (int i = 0; i < 4; i++)
#pragma unroll
                for (int j = 0; j < 4; j++) acc[i][j] += wa[i] * xa[j];
        }
        __syncthreads();
    }

    if (sel == 0) {
        float* Ob = g_Q + (size_t)b * DK * HW;
#pragma unroll
        for (int i = 0; i < 4; i++) {
            float4 o = make_float4(acc[i][0], acc[i][1], acc[i][2], acc[i][3]);
            *(float4*)&Ob[(size_t)(r0 + tr * 4 + i) * HW + p0 + tc * 4] = o;
        }
    } else if (sel == 1) {
        // K: pairs along dk. rows r = tr*4 + i (r0 == 0), cols p = p0 + tc*4 + j
        uint32_t* KH = g_K2H + (size_t)b * (DK / 2) * HW;
        uint32_t* KL = g_K2L + (size_t)b * (DK / 2) * HW;
#pragma unroll
        for (int pr = 0; pr < 2; pr++) {          // pair index: rows (2pr, 2pr+1)
            const int kp = tr * 2 + pr;
#pragma unroll
            for (int j = 0; j < 4; j++) {
                float v0 = acc[pr * 2 + 0][j];
                float v1 = acc[pr * 2 + 1][j];
                __half hh0 = __float2half_rn(v0);
                __half hh1 = __float2half_rn(v1);
                float l0 = v0 - __half2float(hh0);
                float l1 = v1 - __half2float(hh1);
                size_t off = (size_t)kp * HW + p0 + tc * 4 + j;
                KH[off] = h2u(__halves2half2(hh0, hh1));
                KL[off] = packh2(l0, l1);
            }
        }
    } else {
        // V: pairs along hw. rows r, word col = (p0 + tc*4)/2 + {0,1}
        uint32_t* Vg = g_V2 + (size_t)b * DV * (HW / 2);
#pragma unroll
        for (int i = 0; i < 4; i++) {
            const size_t base = (size_t)(r0 + tr * 4 + i) * (HW / 2) + p0 / 2 + tc * 2;
            Vg[base]     = packh2(acc[i][0], acc[i][1]);
            Vg[base + 1] = packh2(acc[i][2], acc[i][3]);
        }
    }
}

// ---------------------------------------------------------------------------
// fp16 mma.sync flash attention with online max (fp16-safe P), pipelined
// cp.async K/V. CTA = (batch, 128-query tile), 512 threads, 64-key tiles.
//   S phase:  warp (mg = w>>2, ng = w&3) -> S[32m x 16n], 3-term fp16 split
//   AV phase: warp (mg, ng) -> O[32m x 64v] (64 fp32 regs/thr), fp16 P/V
// SMEM words (fp16x2): Q2H/Q2L [m][kp] s36, K2H/K2L [kp][n] s68,
//                      V2 [v][np] s36, P2 [m][np] s36
// ---------------------------------------------------------------------------
#define QS2 36
#define KS2 68
#define VS2 36
#define PS2 36
#define WOFF_QH 0
#define WOFF_QL 4608
#define WOFF_KH 9216
#define WOFF_KL 11392
#define WOFF_V  13568
#define WOFF_P  22784
#define SMEM_WORDS 27392    // 109568 bytes

__global__ __launch_bounds__(512, 1) void attn_mma_kernel(float* __restrict__ Out)
{
    extern __shared__ uint32_t sm[];
    __shared__ __align__(16) float s_max[128][4];
    __shared__ float s_part[128][4];
    __shared__ float s_inv[128];

    uint32_t* QH = sm + WOFF_QH;
    uint32_t* QL = sm + WOFF_QL;
    uint32_t* KH = sm + WOFF_KH;
    uint32_t* KL = sm + WOFF_KL;
    uint32_t* VV = sm + WOFF_V;
    uint32_t* PP = sm + WOFF_P;

    const uint32_t SB     = smem_u32(sm);
    const uint32_t kh_dst = SB + WOFF_KH * 4;
    const uint32_t kl_dst = SB + WOFF_KL * 4;
    const uint32_t vv_dst = SB + WOFF_V * 4;

    const int t    = threadIdx.x;
    const int w    = t >> 5;
    const int lane = t & 31;
    const int mg   = w >> 2;          // 0..3 : 32-row group
    const int ng   = w & 3;           // 0..3 : 16-col group (S) / 64-v group (AV)
    const int m0   = mg * 32;
    const int lr   = lane >> 2;       // groupID 0..7
    const int lc   = lane & 3;        // threadID-in-group 0..3
    const int b    = blockIdx.y;
    const int p0   = blockIdx.x * 128;

    const float*    Qb  = g_Q   + (size_t)b * DK * HW;
    const uint32_t* KHg = g_K2H + (size_t)b * (DK / 2) * HW;
    const uint32_t* KLg = g_K2L + (size_t)b * (DK / 2) * HW;
    const uint32_t* Vg  = g_V2  + (size_t)b * DV * (HW / 2);

    // cp.async coordinates
    const int kkp = t >> 4;            // K: 32 rows x 16 chunks = 512 = 1/thread
    const int kc4 = t & 15;

    // ---- issue K[0] then V[0] ----
    {
#pragma unroll
        for (int rep = 0; rep < 1; rep++) {
            uint32_t doff = (uint32_t)(kkp * KS2 + kc4 * 4) * 4;
            cpa16(kh_dst + doff, KHg + (size_t)kkp * HW + kc4 * 4);
            cpa16(kl_dst + doff, KLg + (size_t)kkp * HW + kc4 * 4);
        }
        CP_COMMIT();
#pragma unroll
        for (int j = 0; j < 4; j++) {
            int id = t + j * 512;
            int row = id >> 3, c4 = id & 7;
            cpa16(vv_dst + (uint32_t)(row * VS2 + c4 * 4) * 4,
                  Vg + (size_t)row * (HW / 2) + c4 * 4);
        }
        CP_COMMIT();
    }

    // ---- load + split Q tile [128 m][32 kp] (overlaps inflight cp.async) ----
#pragma unroll
    for (int i = 0; i < 8; i++) {
        int idx = t + i * 512;
        int mm = idx & 127, kp = idx >> 7;
        float q0 = Qb[(size_t)(2 * kp) * HW + p0 + mm];
        float q1 = Qb[(size_t)(2 * kp + 1) * HW + p0 + mm];
        __half h0 = __float2half_rn(q0);
        __half h1 = __float2half_rn(q1);
        QH[mm * QS2 + kp] = h2u(__halves2half2(h0, h1));
        QL[mm * QS2 + kp] = packh2(q0 - __half2float(h0), q1 - __half2float(h1));
    }

    float o[2][8][4];
#pragma unroll
    for (int mt = 0; mt < 2; mt++)
#pragma unroll
        for (int vt = 0; vt < 8; vt++)
#pragma unroll
            for (int j = 0; j < 4; j++) o[mt][vt][j] = 0.f;
    float rs[4]   = {0.f, 0.f, 0.f, 0.f};
    float runm[4] = {-1e30f, -1e30f, -1e30f, -1e30f};

    for (int kt = 0; kt < 64; kt++) {
        // ---- wait K[kt] (V[kt] may stay in flight) ----
        CP_WAIT(1);
        __syncthreads();

        // ---- S = Qh*Kh + Qh*Kl + Ql*Kh (fp16 split, fp32 accum) ----
        float c[2][2][4];
#pragma unroll
        for (int mt = 0; mt < 2; mt++)
#pragma unroll
            for (int nt = 0; nt < 2; nt++)
#pragma unroll
                for (int j = 0; j < 4; j++) c[mt][nt][j] = 0.f;

#pragma unroll
        for (int it = 0; it < 4; it++) {
            const int kw0 = it * 8 + lc;
            uint32_t ah[2][4], al[2][4];
#pragma unroll
            for (int mt = 0; mt < 2; mt++) {
                const int ar = m0 + mt * 16 + lr;
                ah[mt][0] = QH[ar * QS2 + kw0];
                ah[mt][1] = QH[(ar + 8) * QS2 + kw0];
                ah[mt][2] = QH[ar * QS2 + kw0 + 4];
                ah[mt][3] = QH[(ar + 8) * QS2 + kw0 + 4];
                al[mt][0] = QL[ar * QS2 + kw0];
                al[mt][1] = QL[(ar + 8) * QS2 + kw0];
                al[mt][2] = QL[ar * QS2 + kw0 + 4];
                al[mt][3] = QL[(ar + 8) * QS2 + kw0 + 4];
            }
#pragma unroll
            for (int nt = 0; nt < 2; nt++) {
                const int bc = ng * 16 + nt * 8 + lr;
                uint32_t bh0 = KH[kw0 * KS2 + bc];
                uint32_t bh1 = KH[(kw0 + 4) * KS2 + bc];
                uint32_t bl0 = KL[kw0 * KS2 + bc];
                uint32_t bl1 = KL[(kw0 + 4) * KS2 + bc];
#pragma unroll
                for (int mt = 0; mt < 2; mt++) {
                    mma_f16(c[mt][nt], ah[mt], bh0, bh1);
                    mma_f16(c[mt][nt], ah[mt], bl0, bl1);
                    mma_f16(c[mt][nt], al[mt], bh0, bh1);
                }
            }
        }

        // ---- warp-partial row max -> smem ----
#pragma unroll
        for (int mt = 0; mt < 2; mt++) {
            float mx0 = fmaxf(fmaxf(c[mt][0][0], c[mt][0][1]),
                              fmaxf(c[mt][1][0], c[mt][1][1]));
            float mx1 = fmaxf(fmaxf(c[mt][0][2], c[mt][0][3]),
                              fmaxf(c[mt][1][2], c[mt][1][3]));
            mx0 = fmaxf(mx0, __shfl_xor_sync(0xffffffffu, mx0, 1));
            mx0 = fmaxf(mx0, __shfl_xor_sync(0xffffffffu, mx0, 2));
            mx1 = fmaxf(mx1, __shfl_xor_sync(0xffffffffu, mx1, 1));
            mx1 = fmaxf(mx1, __shfl_xor_sync(0xffffffffu, mx1, 2));
            if (lc == 0) {
                s_max[m0 + mt * 16 + lr][ng]     = mx0;
                s_max[m0 + mt * 16 + lr + 8][ng] = mx1;
            }
        }
        __syncthreads();   // K consumed + s_max visible

        // ---- issue K[kt+1] ----
        if (kt < 63) {
            const int n0 = (kt + 1) * 64;
            uint32_t doff = (uint32_t)(kkp * KS2 + kc4 * 4) * 4;
            cpa16(kh_dst + doff, KHg + (size_t)kkp * HW + n0 + kc4 * 4);
            cpa16(kl_dst + doff, KLg + (size_t)kkp * HW + n0 + kc4 * 4);
            CP_COMMIT();
        }

        // ---- tile max, online rescale ----
        float nm[4], corr[4];
#pragma unroll
        for (int s = 0; s < 4; s++) {
            const int row = m0 + (s >> 1) * 16 + (s & 1) * 8 + lr;
            float4 mv = *(const float4*)&s_max[row][0];
            float tmax = fmaxf(fmaxf(mv.x, mv.y), fmaxf(mv.z, mv.w));
            nm[s] = fmaxf(runm[s], tmax);
            corr[s] = __expf(runm[s] - nm[s]);
            rs[s] *= corr[s];
            runm[s] = nm[s];
        }
#pragma unroll
        for (int mt = 0; mt < 2; mt++)
#pragma unroll
            for (int vt = 0; vt < 8; vt++) {
                o[mt][vt][0] *= corr[mt * 2];
                o[mt][vt][1] *= corr[mt * 2];
                o[mt][vt][2] *= corr[mt * 2 + 1];
                o[mt][vt][3] *= corr[mt * 2 + 1];
            }

        // ---- exp, P -> SMEM fp16x2, rowsums ----
#pragma unroll
        for (int mt = 0; mt < 2; mt++) {
            const int row = m0 + mt * 16 + lr;
            const float nm0 = nm[mt * 2], nm1 = nm[mt * 2 + 1];
#pragma unroll
            for (int nt = 0; nt < 2; nt++) {
                const int np = ng * 8 + nt * 4 + lc;
                float e0 = __expf(c[mt][nt][0] - nm0);
                float e1 = __expf(c[mt][nt][1] - nm0);
                float e2 = __expf(c[mt][nt][2] - nm1);
                float e3 = __expf(c[mt][nt][3] - nm1);
                PP[row * PS2 + np]       = packh2(e0, e1);
                PP[(row + 8) * PS2 + np] = packh2(e2, e3);
                rs[mt * 2 + 0] += e0 + e1;
                rs[mt * 2 + 1] += e2 + e3;
            }
        }

        // ---- wait V[kt] (K[kt+1] stays in flight), make V+P visible ----
        if (kt < 63) { CP_WAIT(1); } else { CP_WAIT(0); }
        __syncthreads();

        // ---- O += P * V^T ----
#pragma unroll
        for (int it = 0; it < 4; it++) {
            const int kw0 = it * 8 + lc;
            uint32_t a[2][4];
#pragma unroll
            for (int mt = 0; mt < 2; mt++) {
                const int ar = m0 + mt * 16 + lr;
                a[mt][0] = PP[ar * PS2 + kw0];
                a[mt][1] = PP[(ar + 8) * PS2 + kw0];
                a[mt][2] = PP[ar * PS2 + kw0 + 4];
                a[mt][3] = PP[(ar + 8) * PS2 + kw0 + 4];
            }
#pragma unroll
            for (int vt = 0; vt < 8; vt++) {
                const int vcol = ng * 64 + vt * 8 + lr;
                uint32_t b0 = VV[vcol * VS2 + kw0];
                uint32_t b1 = VV[vcol * VS2 + kw0 + 4];
                mma_f16(o[0][vt], a[0], b0, b1);
                mma_f16(o[1][vt], a[1], b0, b1);
            }
        }

        // ---- V/P consumed; issue V[kt+1] ----
        __syncthreads();
        if (kt < 63) {
            const int nw0 = (kt + 1) * 32;
#pragma unroll
            for (int j = 0; j < 4; j++) {
                int id = t + j * 512;
                int row = id >> 3, c4 = id & 7;
                cpa16(vv_dst + (uint32_t)(row * VS2 + c4 * 4) * 4,
                      Vg + (size_t)row * (HW / 2) + nw0 + c4 * 4);
            }
            CP_COMMIT();
        }
    }

    // ---- rowsum reduction across lanes and ng groups ----
#pragma unroll
    for (int i = 0; i < 4; i++) {
        rs[i] += __shfl_xor_sync(0xffffffffu, rs[i], 1);
        rs[i] += __shfl_xor_sync(0xffffffffu, rs[i], 2);
    }
    if (lc == 0) {
#pragma unroll
        for (int i = 0; i < 4; i++) {
            int row = m0 + (i >> 1) * 16 + (i & 1) * 8 + lr;
            s_part[row][ng] = rs[i];
        }
    }
    __syncthreads();
    if (t < 128)
        s_inv[t] = 1.0f / (s_part[t][0] + s_part[t][1] + s_part[t][2] + s_part[t][3]);
    __syncthreads();

    // ---- normalize + store ----
    float* Ob = Out + (size_t)b * DV * HW;
#pragma unroll
    for (int mt = 0; mt < 2; mt++) {
        const int r = m0 + mt * 16 + lr;
        const float inv0 = s_inv[r];
        const float inv1 = s_inv[r + 8];
#pragma unroll
        for (int vt = 0; vt < 8; vt++) {
            const int v = ng * 64 + vt * 8 + 2 * lc;
            Ob[(size_t)v * HW + p0 + r]           = o[mt][vt][0] * inv0;
            Ob[(size_t)(v + 1) * HW + p0 + r]     = o[mt][vt][1] * inv0;
            Ob[(size_t)v * HW + p0 + r + 8]       = o[mt][vt][2] * inv1;
            Ob[(size_t)(v + 1) * HW + p0 + r + 8] = o[mt][vt][3] * inv1;
        }
    }
}

// ---------------------------------------------------------------------------
extern "C" void kernel_launch(void* const* d_in, const int* in_sizes, int n_in,
                              void* d_out, int out_size)
{
    const float* x  = (const float*)d_in[0];
    const float* qw = (const float*)d_in[1];
    const float* kw = (const float*)d_in[2];
    const float* vw = (const float*)d_in[3];
    float* out = (float*)d_out;

    proj_kernel<<<dim3(64, 1, NB), 256>>>(qw, x, 0);
    proj_kernel<<<dim3(64, 1, NB), 256>>>(kw, x, 1);
    proj_kernel<<<dim3(64, 4, NB), 256>>>(vw, x, 2);

    const size_t smem_bytes = (size_t)SMEM_WORDS * 4;
    cudaFuncSetAttribute(attn_mma_kernel,
                         cudaFuncAttributeMaxDynamicSharedMemorySize,
                         (int)smem_bytes);
    attn_mma_kernel<<<dim3(32, NB), 512, smem_bytes>>>(out);
}